// round 16
// baseline (speedup 1.0000x reference)
#include <cuda_runtime.h>
#include <cuda_fp16.h>
#include <math.h>
#include <stdint.h>

#define S_LEN 4096
#define EMB   768
#define NH    12
#define HD    64
#define QKV_N 2304

// Q pre-scale: (1/sqrt(64)) * log2(e)  -> scores emerge in log2 domain
#define QSCALE 0.18033688f

// Global scratch (allocation-free rule)
__device__ __half g_x_h[(size_t)S_LEN * EMB];
__device__ __half g_qkv_h[(size_t)S_LEN * QKV_N];
__device__ __half g_attn_h[(size_t)S_LEN * EMB];
__device__ __half g_wqkv_t[(size_t)QKV_N * EMB];
__device__ __half g_wout_t[(size_t)EMB * EMB];

// ---------------------------------------------------------------------------
// Helpers
// ---------------------------------------------------------------------------
__device__ __forceinline__ uint32_t smem_u32(const void* p) {
    uint32_t a;
    asm("{ .reg .u64 t; cvta.to.shared.u64 t, %1; cvt.u32.u64 %0, t; }"
        : "=r"(a) : "l"(p));
    return a;
}
__device__ __forceinline__ void ldsm_x4(uint32_t* r, uint32_t a) {
    asm volatile("ldmatrix.sync.aligned.m8n8.x4.shared.b16 {%0,%1,%2,%3}, [%4];"
                 : "=r"(r[0]), "=r"(r[1]), "=r"(r[2]), "=r"(r[3]) : "r"(a));
}
__device__ __forceinline__ void ldsm_x4t(uint32_t* r, uint32_t a) {
    asm volatile("ldmatrix.sync.aligned.m8n8.x4.trans.shared.b16 {%0,%1,%2,%3}, [%4];"
                 : "=r"(r[0]), "=r"(r[1]), "=r"(r[2]), "=r"(r[3]) : "r"(a));
}
// f32-accumulate fp16 mma
__device__ __forceinline__ void mma_f16(float c[4], const uint32_t a[4],
                                        uint32_t b0, uint32_t b1) {
    asm volatile(
        "mma.sync.aligned.m16n8k16.row.col.f32.f16.f16.f32 "
        "{%0,%1,%2,%3}, {%4,%5,%6,%7}, {%8,%9}, {%0,%1,%2,%3};"
        : "+f"(c[0]), "+f"(c[1]), "+f"(c[2]), "+f"(c[3])
        : "r"(a[0]), "r"(a[1]), "r"(a[2]), "r"(a[3]), "r"(b0), "r"(b1));
}
// f16-accumulate fp16 mma (scores; packed f16x2 output feeds ex2 directly)
__device__ __forceinline__ void mma_f16acc(uint32_t c[2], const uint32_t a[4],
                                           uint32_t b0, uint32_t b1) {
    asm volatile(
        "mma.sync.aligned.m16n8k16.row.col.f16.f16.f16.f16 "
        "{%0,%1}, {%2,%3,%4,%5}, {%6,%7}, {%0,%1};"
        : "+r"(c[0]), "+r"(c[1])
        : "r"(a[0]), "r"(a[1]), "r"(a[2]), "r"(a[3]), "r"(b0), "r"(b1));
}
__device__ __forceinline__ void cp16(uint32_t dst, const void* src) {
    asm volatile("cp.async.cg.shared.global [%0], [%1], 16;"
                 :: "r"(dst), "l"(src) : "memory");
}
__device__ __forceinline__ void cp_commit() {
    asm volatile("cp.async.commit_group;" ::: "memory");
}
template<int N> __device__ __forceinline__ void cp_wait() {
    asm volatile("cp.async.wait_group %0;" :: "n"(N) : "memory");
}
__device__ __forceinline__ __half2 h2(float a, float b) {
    return __floats2half2_rn(a, b);
}
__device__ __forceinline__ uint32_t ex2_h2(uint32_t x) {
    uint32_t r;
    asm("ex2.approx.f16x2 %0, %1;" : "=r"(r) : "r"(x));
    return r;
}
#define ONES_H2 0x3C003C00u   // half2(1.0, 1.0)

// ---------------------------------------------------------------------------
// fp32 -> half conversion (x)
// ---------------------------------------------------------------------------
__global__ void f32_to_h(const float* __restrict__ x, __half* __restrict__ y) {
    int i = (blockIdx.x * blockDim.x + threadIdx.x) * 4;
    float4 v = *(const float4*)(x + i);
    *(__half2*)(y + i)     = h2(v.x, v.y);
    *(__half2*)(y + i + 2) = h2(v.z, v.w);
}

// ---------------------------------------------------------------------------
// Weight transpose + fp32->half: W[K][N] -> WT[N][K]
// ---------------------------------------------------------------------------
__global__ void transpose_to_half(const float* __restrict__ W,
                                  __half* __restrict__ WT, int K, int N)
{
    __shared__ float t[32][33];
    int n0 = blockIdx.x * 32, k0 = blockIdx.y * 32;
    int tx = threadIdx.x, ty = threadIdx.y;      // 32 x 8
    #pragma unroll
    for (int i = 0; i < 32; i += 8)
        t[ty + i][tx] = W[(size_t)(k0 + ty + i) * N + n0 + tx];
    __syncthreads();
    #pragma unroll
    for (int i = 0; i < 32; i += 8)
        WT[(size_t)(n0 + ty + i) * K + k0 + tx] = __float2half_rn(t[tx][ty + i]);
}

// ---------------------------------------------------------------------------
// fp16 GEMM, 4-stage cp.async ring, k-chunk 32, wait<2> (2 iterations of
// DRAM-latency slack), ONE barrier per iteration. Dynamic smem 80 KB,
// 128x128 block tile, 256 threads = 8 warps of 32x64, 2 CTA/SM.
// MODE 0: C half, cols<EMB scaled by QSCALE (QKV). MODE 1: C fp32 (out-proj).
// ---------------------------------------------------------------------------
#define GS 40                         // halves per smem row
#define STAGE (128 * GS * 2)          // 10240 bytes per array per stage
#define G_STG 4
#define GEMM_SMEM (2 * G_STG * STAGE) // 81920: A0..A3 | B0..B3

template<int MODE>
__global__ __launch_bounds__(256, 2) void gemm_f16(
    const __half* __restrict__ A, const __half* __restrict__ Bt,
    const float* __restrict__ bias, void* __restrict__ Cp,
    int M, int N, int K)
{
    extern __shared__ char gsm[];
    const uint32_t sA0 = smem_u32(gsm);
    const uint32_t sB0 = sA0 + G_STG * STAGE;

    const int tid  = threadIdx.x;
    const int lane = tid & 31;
    const int warp = tid >> 5;
    const int wm = (warp >> 1) * 32;
    const int wn = (warp & 1) * 64;
    const int bm = blockIdx.y * 128;
    const int bn = blockIdx.x * 128;
    const int lr = lane >> 2;
    const int lc = lane & 3;

    float acc[2][8][4];
    #pragma unroll
    for (int i = 0; i < 2; ++i)
        #pragma unroll
        for (int j = 0; j < 8; ++j)
            #pragma unroll
            for (int f = 0; f < 4; ++f) acc[i][j][f] = 0.0f;

    const uint32_t a_lane = (uint32_t)((wm + (lane & 15)) * GS
                                       + ((lane >> 4) & 1) * 8) * 2;
    const uint32_t b_lane = (uint32_t)((wn + ((lane >> 4) & 1) * 8 + (lane & 7)) * GS
                                       + ((lane >> 3) & 1) * 8) * 2;

    // Prologue: stages 0..2 (each: A,B 512 chunks -> 2/thread each)
    #pragma unroll
    for (int s = 0; s < 3; ++s) {
        const int k0 = s * 32;
        const uint32_t dA = sA0 + s * STAGE;
        const uint32_t dB = sB0 + s * STAGE;
        #pragma unroll
        for (int u = 0; u < 2; ++u) {
            int c = tid + u * 256;
            int r = c >> 2;
            int off = (c & 3) << 3;
            cp16(dA + (uint32_t)(r * GS + off) * 2, A  + (size_t)(bm + r) * K + k0 + off);
            cp16(dB + (uint32_t)(r * GS + off) * 2, Bt + (size_t)(bn + r) * K + k0 + off);
        }
        cp_commit();
    }

    const int nk = K / 32;   // 24
    for (int kt = 0; kt < nk; ++kt) {
        cp_wait<2>();
        __syncthreads();

        // Refill stage (kt+3)&3: its last reads happened in iteration kt-1,
        // ordered before this point by the barrier above.
        if (kt + 3 < nk) {
            const int k0 = (kt + 3) * 32;
            const uint32_t dA = sA0 + ((kt + 3) & 3) * STAGE;
            const uint32_t dB = sB0 + ((kt + 3) & 3) * STAGE;
            #pragma unroll
            for (int u = 0; u < 2; ++u) {
                int c = tid + u * 256;
                int r = c >> 2;
                int off = (c & 3) << 3;
                cp16(dA + (uint32_t)(r * GS + off) * 2, A  + (size_t)(bm + r) * K + k0 + off);
                cp16(dB + (uint32_t)(r * GS + off) * 2, Bt + (size_t)(bn + r) * K + k0 + off);
            }
        }
        cp_commit();

        const uint32_t sA = sA0 + (kt & 3) * STAGE;
        const uint32_t sB = sB0 + (kt & 3) * STAGE;
        #pragma unroll
        for (int kk = 0; kk < 2; ++kk) {
            const uint32_t kb2 = kk * 32;
            uint32_t a[2][4], b[4][4];
            #pragma unroll
            for (int i = 0; i < 2; ++i)
                ldsm_x4(a[i], sA + a_lane + (uint32_t)(i * 16 * GS * 2) + kb2);
            #pragma unroll
            for (int g = 0; g < 4; ++g)
                ldsm_x4(b[g], sB + b_lane + (uint32_t)(g * 16 * GS * 2) + kb2);
            #pragma unroll
            for (int i = 0; i < 2; ++i)
                #pragma unroll
                for (int g = 0; g < 4; ++g) {
                    mma_f16(acc[i][2 * g],     a[i], b[g][0], b[g][1]);
                    mma_f16(acc[i][2 * g + 1], a[i], b[g][2], b[g][3]);
                }
        }
    }

    __syncthreads();   // last stage reads done before epilogue reuses nothing, but keep order
    #pragma unroll
    for (int i = 0; i < 2; ++i) {
        int row = bm + wm + i * 16 + lr;
        #pragma unroll
        for (int j = 0; j < 8; ++j) {
            int col = bn + wn + j * 8 + 2 * lc;
            float b0 = bias[col], b1 = bias[col + 1];
            if (MODE == 0) {
                float sc = (col < EMB) ? QSCALE : 1.0f;
                __half* C = (__half*)Cp;
                *(__half2*)(C + (size_t)row * N + col) =
                    h2((acc[i][j][0] + b0) * sc, (acc[i][j][1] + b1) * sc);
                *(__half2*)(C + (size_t)(row + 8) * N + col) =
                    h2((acc[i][j][2] + b0) * sc, (acc[i][j][3] + b1) * sc);
            } else {
                float* C = (float*)Cp;
                *(float2*)(C + (size_t)row * N + col) =
                    make_float2(acc[i][j][0] + b0, acc[i][j][1] + b1);
                *(float2*)(C + (size_t)(row + 8) * N + col) =
                    make_float2(acc[i][j][2] + b0, acc[i][j][3] + b1);
            }
        }
    }
}

// ---------------------------------------------------------------------------
// fp16 flash attention (unchanged from R15). Block = (head, 128 q rows),
// 128 threads = 4 warps x 32 q rows. Ring-3 cp.async (72KB -> 3 CTA/SM,
// single wave). f16-acc S-mma -> ex2.approx.f16x2; l via ones-column mma.
// ---------------------------------------------------------------------------
#define KS_H   72
#define SM_Q   0
#define SM_KV  18432
#define N_STG  3
#define SM_ATT (18432 + N_STG * 18432)   // 73728 bytes

__global__ void __launch_bounds__(128, 3) attn_f16(
    const __half* __restrict__ qkv, __half* __restrict__ outh)
{
    extern __shared__ char smem[];
    const uint32_t sb = smem_u32(smem);

    const int tid  = threadIdx.x;
    const int lane = tid & 31;
    const int wid  = tid >> 5;
    const int m0 = wid * 32;
    const int lr = lane >> 2;
    const int lc = lane & 3;
    const int h  = blockIdx.y;
    const int q0 = blockIdx.x * 128;

    const __half* Qg = qkv + h * HD;
    const __half* Kg = qkv + EMB + h * HD;
    const __half* Vg = qkv + 2 * EMB + h * HD;

    #pragma unroll
    for (int u = 0; u < 8; ++u) {
        int c = tid + u * 128;
        int r = c >> 3;
        int off = (c & 7) << 3;
        cp16(sb + SM_Q + (uint32_t)(r * KS_H + off) * 2,
             Qg + (size_t)(q0 + r) * QKV_N + off);
    }
    cp_commit();
    #pragma unroll
    for (int s = 0; s < 2; ++s) {
        const int kb = s * 64;
        const uint32_t dK = sb + SM_KV + s * 18432;
        #pragma unroll
        for (int u = 0; u < 4; ++u) {
            int c = tid + u * 128;
            int r = c >> 3;
            int off = (c & 7) << 3;
            cp16(dK + (uint32_t)(r * KS_H + off) * 2,        Kg + (size_t)(kb + r) * QKV_N + off);
            cp16(dK + 9216 + (uint32_t)(r * KS_H + off) * 2, Vg + (size_t)(kb + r) * QKV_N + off);
        }
        cp_commit();
    }

    const uint32_t qp_lane = (uint32_t)((m0 + (lane & 15)) * KS_H
                                        + ((lane >> 4) & 1) * 8) * 2;
    const uint32_t k_lane = (uint32_t)((((lane >> 4) & 1) * 8 + (lane & 7)) * KS_H
                                       + ((lane >> 3) & 1) * 8) * 2;
    const uint32_t v_lane = (uint32_t)((lane & 15) * KS_H
                                       + ((lane >> 4) & 1) * 8) * 2;

    uint32_t qf[4][2][4];
    float lacc[2][4] = {{0,0,0,0},{0,0,0,0}};
    float o[2][8][4];
    #pragma unroll
    for (int t = 0; t < 2; ++t)
        #pragma unroll
        for (int n = 0; n < 8; ++n)
            #pragma unroll
            for (int f = 0; f < 4; ++f) o[t][n][f] = 0.0f;

    int stg = 0;
    for (int jt = 0; jt < 64; ++jt) {
        cp_wait<1>();
        __syncthreads();

        if (jt == 0) {
            #pragma unroll
            for (int kk = 0; kk < 4; ++kk)
                #pragma unroll
                for (int t = 0; t < 2; ++t)
                    ldsm_x4(qf[kk][t], sb + SM_Q + qp_lane
                            + (uint32_t)(t * 16 * KS_H * 2) + kk * 32);
        }

        if (jt + 2 < 64) {
            const int kb = (jt + 2) * 64;
            int rs = stg + 2; if (rs >= N_STG) rs -= N_STG;
            const uint32_t dK = sb + SM_KV + rs * 18432;
            #pragma unroll
            for (int u = 0; u < 4; ++u) {
                int c = tid + u * 128;
                int r = c >> 3;
                int off = (c & 7) << 3;
                cp16(dK + (uint32_t)(r * KS_H + off) * 2,        Kg + (size_t)(kb + r) * QKV_N + off);
                cp16(dK + 9216 + (uint32_t)(r * KS_H + off) * 2, Vg + (size_t)(kb + r) * QKV_N + off);
            }
        }
        cp_commit();

        const uint32_t sK = sb + SM_KV + stg * 18432;
        const uint32_t sV = sK + 9216;

        uint32_t s16[2][8][2];
        #pragma unroll
        for (int t = 0; t < 2; ++t)
            #pragma unroll
            for (int n = 0; n < 8; ++n) {
                s16[t][n][0] = 0u; s16[t][n][1] = 0u;
            }
        #pragma unroll
        for (int kk = 0; kk < 4; ++kk) {
            #pragma unroll
            for (int g = 0; g < 4; ++g) {
                uint32_t b[4];
                ldsm_x4(b, sK + k_lane + (uint32_t)(g * 16 * KS_H * 2) + kk * 32);
                #pragma unroll
                for (int t = 0; t < 2; ++t) {
                    mma_f16acc(s16[t][2 * g],     qf[kk][t], b[0], b[1]);
                    mma_f16acc(s16[t][2 * g + 1], qf[kk][t], b[2], b[3]);
                }
            }
        }

        uint32_t pa[2][4][4];
        #pragma unroll
        for (int t = 0; t < 2; ++t)
            #pragma unroll
            for (int kk = 0; kk < 4; ++kk) {
                const int n0 = 2 * kk, n1 = 2 * kk + 1;
                pa[t][kk][0] = ex2_h2(s16[t][n0][0]);
                pa[t][kk][1] = ex2_h2(s16[t][n0][1]);
                pa[t][kk][2] = ex2_h2(s16[t][n1][0]);
                pa[t][kk][3] = ex2_h2(s16[t][n1][1]);
            }

        #pragma unroll
        for (int kk = 0; kk < 4; ++kk) {
            #pragma unroll
            for (int g = 0; g < 4; ++g) {
                uint32_t vb[4];
                ldsm_x4t(vb, sV + v_lane + (uint32_t)(kk * 16 * KS_H * 2) + g * 32);
                #pragma unroll
                for (int t = 0; t < 2; ++t) {
                    mma_f16(o[t][2 * g],     pa[t][kk], vb[0], vb[1]);
                    mma_f16(o[t][2 * g + 1], pa[t][kk], vb[2], vb[3]);
                }
            }
            #pragma unroll
            for (int t = 0; t < 2; ++t)
                mma_f16(lacc[t], pa[t][kk], ONES_H2, ONES_H2);
        }

        if (++stg == N_STG) stg = 0;
    }

    #pragma unroll
    for (int t = 0; t < 2; ++t) {
        float inv_lo = 1.0f / lacc[t][0];
        float inv_hi = 1.0f / lacc[t][2];
        int row = q0 + m0 + t * 16 + lr;
        #pragma unroll
        for (int n = 0; n < 8; ++n) {
            int col = h * HD + n * 8 + 2 * lc;
            *(__half2*)(outh + (size_t)row * EMB + col) =
                h2(o[t][n][0] * inv_lo, o[t][n][1] * inv_lo);
            *(__half2*)(outh + (size_t)(row + 8) * EMB + col) =
                h2(o[t][n][2] * inv_hi, o[t][n][3] * inv_hi);
        }
    }
}

// ---------------------------------------------------------------------------
extern "C" void kernel_launch(void* const* d_in, const int* in_sizes, int n_in,
                              void* d_out, int out_size)
{
    const float* x     = (const float*)d_in[0];
    const float* w_qkv = (const float*)d_in[1];
    const float* b_qkv = (const float*)d_in[2];
    const float* w_out = (const float*)d_in[3];
    const float* b_out = (const float*)d_in[4];
    float* out = (float*)d_out;

    __half *xh, *qkv_h, *attn_h, *wqkv_t, *wout_t;
    cudaGetSymbolAddress((void**)&xh,     g_x_h);
    cudaGetSymbolAddress((void**)&qkv_h,  g_qkv_h);
    cudaGetSymbolAddress((void**)&attn_h, g_attn_h);
    cudaGetSymbolAddress((void**)&wqkv_t, g_wqkv_t);
    cudaGetSymbolAddress((void**)&wout_t, g_wout_t);

    // 0) Conversions
    f32_to_h<<<(S_LEN * EMB) / (256 * 4), 256>>>(x, xh);
    transpose_to_half<<<dim3(QKV_N / 32, EMB / 32), dim3(32, 8)>>>(w_qkv, wqkv_t, EMB, QKV_N);
    transpose_to_half<<<dim3(EMB / 32,  EMB / 32), dim3(32, 8)>>>(w_out, wout_t, EMB, EMB);

    // 1) QKV projection (Q cols pre-scaled by QSCALE)
    {
        cudaFuncSetAttribute(gemm_f16<0>,
                             cudaFuncAttributeMaxDynamicSharedMemorySize, GEMM_SMEM);
        dim3 grid(QKV_N / 128, S_LEN / 128);
        gemm_f16<0><<<grid, 256, GEMM_SMEM>>>(xh, wqkv_t, b_qkv, qkv_h,
                                              S_LEN, QKV_N, EMB);
    }

    // 2) Flash attention (ring-3, 3 CTA/SM, single wave)
    {
        cudaFuncSetAttribute(attn_f16,
                             cudaFuncAttributeMaxDynamicSharedMemorySize, SM_ATT);
        dim3 grid(S_LEN / 128, NH);
        attn_f16<<<grid, 128, SM_ATT>>>(qkv_h, attn_h);
    }

    // 3) Output projection -> fp32
    {
        cudaFuncSetAttribute(gemm_f16<1>,
                             cudaFuncAttributeMaxDynamicSharedMemorySize, GEMM_SMEM);
        dim3 grid(EMB / 128, S_LEN / 128);
        gemm_f16<1><<<grid, 256, GEMM_SMEM>>>(attn_h, wout_t, b_out, out,
                                              S_LEN, EMB, EMB);
    }
}

// round 17
// speedup vs baseline: 1.0288x; 1.0288x over previous
#include <cuda_runtime.h>
#include <cuda_fp16.h>
#include <math.h>
#include <stdint.h>

#define S_LEN 4096
#define EMB   768
#define NH    12
#define HD    64
#define QKV_N 2304

// Q pre-scale: (1/sqrt(64)) * log2(e)  -> scores emerge in log2 domain
#define QSCALE 0.18033688f

// Global scratch (allocation-free rule)
__device__ __half g_x_h[(size_t)S_LEN * EMB];
__device__ __half g_qkv_h[(size_t)S_LEN * QKV_N];
__device__ __half g_attn_h[(size_t)S_LEN * EMB];
__device__ __half g_wqkv_t[(size_t)QKV_N * EMB];
__device__ __half g_wout_t[(size_t)EMB * EMB];

// ---------------------------------------------------------------------------
// Helpers
// ---------------------------------------------------------------------------
__device__ __forceinline__ uint32_t smem_u32(const void* p) {
    uint32_t a;
    asm("{ .reg .u64 t; cvta.to.shared.u64 t, %1; cvt.u32.u64 %0, t; }"
        : "=r"(a) : "l"(p));
    return a;
}
__device__ __forceinline__ void ldsm_x4(uint32_t* r, uint32_t a) {
    asm volatile("ldmatrix.sync.aligned.m8n8.x4.shared.b16 {%0,%1,%2,%3}, [%4];"
                 : "=r"(r[0]), "=r"(r[1]), "=r"(r[2]), "=r"(r[3]) : "r"(a));
}
__device__ __forceinline__ void ldsm_x4t(uint32_t* r, uint32_t a) {
    asm volatile("ldmatrix.sync.aligned.m8n8.x4.trans.shared.b16 {%0,%1,%2,%3}, [%4];"
                 : "=r"(r[0]), "=r"(r[1]), "=r"(r[2]), "=r"(r[3]) : "r"(a));
}
// f32-accumulate fp16 mma
__device__ __forceinline__ void mma_f16(float c[4], const uint32_t a[4],
                                        uint32_t b0, uint32_t b1) {
    asm volatile(
        "mma.sync.aligned.m16n8k16.row.col.f32.f16.f16.f32 "
        "{%0,%1,%2,%3}, {%4,%5,%6,%7}, {%8,%9}, {%0,%1,%2,%3};"
        : "+f"(c[0]), "+f"(c[1]), "+f"(c[2]), "+f"(c[3])
        : "r"(a[0]), "r"(a[1]), "r"(a[2]), "r"(a[3]), "r"(b0), "r"(b1));
}
// f16-accumulate fp16 mma (scores; packed f16x2 output feeds ex2 directly)
__device__ __forceinline__ void mma_f16acc(uint32_t c[2], const uint32_t a[4],
                                           uint32_t b0, uint32_t b1) {
    asm volatile(
        "mma.sync.aligned.m16n8k16.row.col.f16.f16.f16.f16 "
        "{%0,%1}, {%2,%3,%4,%5}, {%6,%7}, {%0,%1};"
        : "+r"(c[0]), "+r"(c[1])
        : "r"(a[0]), "r"(a[1]), "r"(a[2]), "r"(a[3]), "r"(b0), "r"(b1));
}
__device__ __forceinline__ void cp16(uint32_t dst, const void* src) {
    asm volatile("cp.async.cg.shared.global [%0], [%1], 16;"
                 :: "r"(dst), "l"(src) : "memory");
}
__device__ __forceinline__ void cp_commit() {
    asm volatile("cp.async.commit_group;" ::: "memory");
}
template<int N> __device__ __forceinline__ void cp_wait() {
    asm volatile("cp.async.wait_group %0;" :: "n"(N) : "memory");
}
__device__ __forceinline__ __half2 h2(float a, float b) {
    return __floats2half2_rn(a, b);
}
__device__ __forceinline__ uint32_t ex2_h2(uint32_t x) {
    uint32_t r;
    asm("ex2.approx.f16x2 %0, %1;" : "=r"(r) : "r"(x));
    return r;
}
#define ONES_H2 0x3C003C00u   // half2(1.0, 1.0)

// ---------------------------------------------------------------------------
// fp32 -> half conversion (x)
// ---------------------------------------------------------------------------
__global__ void f32_to_h(const float* __restrict__ x, __half* __restrict__ y) {
    int i = (blockIdx.x * blockDim.x + threadIdx.x) * 4;
    float4 v = *(const float4*)(x + i);
    *(__half2*)(y + i)     = h2(v.x, v.y);
    *(__half2*)(y + i + 2) = h2(v.z, v.w);
}

// ---------------------------------------------------------------------------
// Weight transpose + fp32->half: W[K][N] -> WT[N][K]
// ---------------------------------------------------------------------------
__global__ void transpose_to_half(const float* __restrict__ W,
                                  __half* __restrict__ WT, int K, int N)
{
    __shared__ float t[32][33];
    int n0 = blockIdx.x * 32, k0 = blockIdx.y * 32;
    int tx = threadIdx.x, ty = threadIdx.y;      // 32 x 8
    #pragma unroll
    for (int i = 0; i < 32; i += 8)
        t[ty + i][tx] = W[(size_t)(k0 + ty + i) * N + n0 + tx];
    __syncthreads();
    #pragma unroll
    for (int i = 0; i < 32; i += 8)
        WT[(size_t)(n0 + ty + i) * K + k0 + tx] = __float2half_rn(t[tx][ty + i]);
}

// ---------------------------------------------------------------------------
// fp16 GEMM: k-chunk 64 (long bursts, 12 iters for K=768) + 3-stage cp.async
// ring with wait<1> (one full iteration of DRAM slack) + ONE barrier/iter.
// Dynamic smem 108 KB -> 2 CTA/SM. 128x128 block, 256 thr = 8 warps of 32x64.
// MODE 0: C half, cols<EMB scaled by QSCALE (QKV). MODE 1: C fp32 (out-proj).
// ---------------------------------------------------------------------------
#define GS2 72                        // halves per smem row (64 data + 8 pad)
#define STG2 (128 * GS2 * 2)          // 18432 bytes per array per stage
#define G_STG 3
#define GEMM_SMEM (2 * G_STG * STG2)  // 110592: A0..A2 | B0..B2

template<int MODE>
__global__ __launch_bounds__(256, 2) void gemm_f16(
    const __half* __restrict__ A, const __half* __restrict__ Bt,
    const float* __restrict__ bias, void* __restrict__ Cp,
    int M, int N, int K)
{
    extern __shared__ char gsm[];
    const uint32_t sA0 = smem_u32(gsm);
    const uint32_t sB0 = sA0 + G_STG * STG2;

    const int tid  = threadIdx.x;
    const int lane = tid & 31;
    const int warp = tid >> 5;
    const int wm = (warp >> 1) * 32;
    const int wn = (warp & 1) * 64;
    const int bm = blockIdx.y * 128;
    const int bn = blockIdx.x * 128;
    const int lr = lane >> 2;
    const int lc = lane & 3;

    float acc[2][8][4];
    #pragma unroll
    for (int i = 0; i < 2; ++i)
        #pragma unroll
        for (int j = 0; j < 8; ++j)
            #pragma unroll
            for (int f = 0; f < 4; ++f) acc[i][j][f] = 0.0f;

    const uint32_t a_lane = (uint32_t)((wm + (lane & 15)) * GS2
                                       + ((lane >> 4) & 1) * 8) * 2;
    const uint32_t b_lane = (uint32_t)((wn + ((lane >> 4) & 1) * 8 + (lane & 7)) * GS2
                                       + ((lane >> 3) & 1) * 8) * 2;

    // Prologue: stages 0..1 (each: A,B 1024 chunks -> 4/thread each)
    #pragma unroll
    for (int s = 0; s < 2; ++s) {
        const int k0 = s * 64;
        const uint32_t dA = sA0 + s * STG2;
        const uint32_t dB = sB0 + s * STG2;
        #pragma unroll
        for (int u = 0; u < 4; ++u) {
            int c = tid + u * 256;
            int r = c >> 3;
            int off = (c & 7) << 3;
            cp16(dA + (uint32_t)(r * GS2 + off) * 2, A  + (size_t)(bm + r) * K + k0 + off);
            cp16(dB + (uint32_t)(r * GS2 + off) * 2, Bt + (size_t)(bn + r) * K + k0 + off);
        }
        cp_commit();
    }

    const int nk = K / 64;   // 12
    int stg = 0;
    for (int kt = 0; kt < nk; ++kt) {
        cp_wait<1>();
        __syncthreads();

        // Refill stage (kt+2)%3: its reads happened in iteration kt-1,
        // ordered before this point by the barrier above.
        if (kt + 2 < nk) {
            const int k0 = (kt + 2) * 64;
            int rs = stg + 2; if (rs >= G_STG) rs -= G_STG;
            const uint32_t dA = sA0 + rs * STG2;
            const uint32_t dB = sB0 + rs * STG2;
            #pragma unroll
            for (int u = 0; u < 4; ++u) {
                int c = tid + u * 256;
                int r = c >> 3;
                int off = (c & 7) << 3;
                cp16(dA + (uint32_t)(r * GS2 + off) * 2, A  + (size_t)(bm + r) * K + k0 + off);
                cp16(dB + (uint32_t)(r * GS2 + off) * 2, Bt + (size_t)(bn + r) * K + k0 + off);
            }
        }
        cp_commit();

        const uint32_t sA = sA0 + stg * STG2;
        const uint32_t sB = sB0 + stg * STG2;
        #pragma unroll
        for (int kk = 0; kk < 4; ++kk) {
            const uint32_t kb2 = kk * 32;
            uint32_t a[2][4], b[4][4];
            #pragma unroll
            for (int i = 0; i < 2; ++i)
                ldsm_x4(a[i], sA + a_lane + (uint32_t)(i * 16 * GS2 * 2) + kb2);
            #pragma unroll
            for (int g = 0; g < 4; ++g)
                ldsm_x4(b[g], sB + b_lane + (uint32_t)(g * 16 * GS2 * 2) + kb2);
            #pragma unroll
            for (int i = 0; i < 2; ++i)
                #pragma unroll
                for (int g = 0; g < 4; ++g) {
                    mma_f16(acc[i][2 * g],     a[i], b[g][0], b[g][1]);
                    mma_f16(acc[i][2 * g + 1], a[i], b[g][2], b[g][3]);
                }
        }

        if (++stg == G_STG) stg = 0;
    }

    #pragma unroll
    for (int i = 0; i < 2; ++i) {
        int row = bm + wm + i * 16 + lr;
        #pragma unroll
        for (int j = 0; j < 8; ++j) {
            int col = bn + wn + j * 8 + 2 * lc;
            float b0 = bias[col], b1 = bias[col + 1];
            if (MODE == 0) {
                float sc = (col < EMB) ? QSCALE : 1.0f;
                __half* C = (__half*)Cp;
                *(__half2*)(C + (size_t)row * N + col) =
                    h2((acc[i][j][0] + b0) * sc, (acc[i][j][1] + b1) * sc);
                *(__half2*)(C + (size_t)(row + 8) * N + col) =
                    h2((acc[i][j][2] + b0) * sc, (acc[i][j][3] + b1) * sc);
            } else {
                float* C = (float*)Cp;
                *(float2*)(C + (size_t)row * N + col) =
                    make_float2(acc[i][j][0] + b0, acc[i][j][1] + b1);
                *(float2*)(C + (size_t)(row + 8) * N + col) =
                    make_float2(acc[i][j][2] + b0, acc[i][j][3] + b1);
            }
        }
    }
}

// ---------------------------------------------------------------------------
// fp16 flash attention (unchanged from R15). Block = (head, 128 q rows),
// 128 threads = 4 warps x 32 q rows. Ring-3 cp.async (72KB -> 3 CTA/SM,
// single wave). f16-acc S-mma -> ex2.approx.f16x2; l via ones-column mma.
// ---------------------------------------------------------------------------
#define KS_H   72
#define SM_Q   0
#define SM_KV  18432
#define N_STG  3
#define SM_ATT (18432 + N_STG * 18432)   // 73728 bytes

__global__ void __launch_bounds__(128, 3) attn_f16(
    const __half* __restrict__ qkv, __half* __restrict__ outh)
{
    extern __shared__ char smem[];
    const uint32_t sb = smem_u32(smem);

    const int tid  = threadIdx.x;
    const int lane = tid & 31;
    const int wid  = tid >> 5;
    const int m0 = wid * 32;
    const int lr = lane >> 2;
    const int lc = lane & 3;
    const int h  = blockIdx.y;
    const int q0 = blockIdx.x * 128;

    const __half* Qg = qkv + h * HD;
    const __half* Kg = qkv + EMB + h * HD;
    const __half* Vg = qkv + 2 * EMB + h * HD;

    #pragma unroll
    for (int u = 0; u < 8; ++u) {
        int c = tid + u * 128;
        int r = c >> 3;
        int off = (c & 7) << 3;
        cp16(sb + SM_Q + (uint32_t)(r * KS_H + off) * 2,
             Qg + (size_t)(q0 + r) * QKV_N + off);
    }
    cp_commit();
    #pragma unroll
    for (int s = 0; s < 2; ++s) {
        const int kb = s * 64;
        const uint32_t dK = sb + SM_KV + s * 18432;
        #pragma unroll
        for (int u = 0; u < 4; ++u) {
            int c = tid + u * 128;
            int r = c >> 3;
            int off = (c & 7) << 3;
            cp16(dK + (uint32_t)(r * KS_H + off) * 2,        Kg + (size_t)(kb + r) * QKV_N + off);
            cp16(dK + 9216 + (uint32_t)(r * KS_H + off) * 2, Vg + (size_t)(kb + r) * QKV_N + off);
        }
        cp_commit();
    }

    const uint32_t qp_lane = (uint32_t)((m0 + (lane & 15)) * KS_H
                                        + ((lane >> 4) & 1) * 8) * 2;
    const uint32_t k_lane = (uint32_t)((((lane >> 4) & 1) * 8 + (lane & 7)) * KS_H
                                       + ((lane >> 3) & 1) * 8) * 2;
    const uint32_t v_lane = (uint32_t)((lane & 15) * KS_H
                                       + ((lane >> 4) & 1) * 8) * 2;

    uint32_t qf[4][2][4];
    float lacc[2][4] = {{0,0,0,0},{0,0,0,0}};
    float o[2][8][4];
    #pragma unroll
    for (int t = 0; t < 2; ++t)
        #pragma unroll
        for (int n = 0; n < 8; ++n)
            #pragma unroll
            for (int f = 0; f < 4; ++f) o[t][n][f] = 0.0f;

    int stg = 0;
    for (int jt = 0; jt < 64; ++jt) {
        cp_wait<1>();
        __syncthreads();

        if (jt == 0) {
            #pragma unroll
            for (int kk = 0; kk < 4; ++kk)
                #pragma unroll
                for (int t = 0; t < 2; ++t)
                    ldsm_x4(qf[kk][t], sb + SM_Q + qp_lane
                            + (uint32_t)(t * 16 * KS_H * 2) + kk * 32);
        }

        if (jt + 2 < 64) {
            const int kb = (jt + 2) * 64;
            int rs = stg + 2; if (rs >= N_STG) rs -= N_STG;
            const uint32_t dK = sb + SM_KV + rs * 18432;
            #pragma unroll
            for (int u = 0; u < 4; ++u) {
                int c = tid + u * 128;
                int r = c >> 3;
                int off = (c & 7) << 3;
                cp16(dK + (uint32_t)(r * KS_H + off) * 2,        Kg + (size_t)(kb + r) * QKV_N + off);
                cp16(dK + 9216 + (uint32_t)(r * KS_H + off) * 2, Vg + (size_t)(kb + r) * QKV_N + off);
            }
        }
        cp_commit();

        const uint32_t sK = sb + SM_KV + stg * 18432;
        const uint32_t sV = sK + 9216;

        uint32_t s16[2][8][2];
        #pragma unroll
        for (int t = 0; t < 2; ++t)
            #pragma unroll
            for (int n = 0; n < 8; ++n) {
                s16[t][n][0] = 0u; s16[t][n][1] = 0u;
            }
        #pragma unroll
        for (int kk = 0; kk < 4; ++kk) {
            #pragma unroll
            for (int g = 0; g < 4; ++g) {
                uint32_t b[4];
                ldsm_x4(b, sK + k_lane + (uint32_t)(g * 16 * KS_H * 2) + kk * 32);
                #pragma unroll
                for (int t = 0; t < 2; ++t) {
                    mma_f16acc(s16[t][2 * g],     qf[kk][t], b[0], b[1]);
                    mma_f16acc(s16[t][2 * g + 1], qf[kk][t], b[2], b[3]);
                }
            }
        }

        uint32_t pa[2][4][4];
        #pragma unroll
        for (int t = 0; t < 2; ++t)
            #pragma unroll
            for (int kk = 0; kk < 4; ++kk) {
                const int n0 = 2 * kk, n1 = 2 * kk + 1;
                pa[t][kk][0] = ex2_h2(s16[t][n0][0]);
                pa[t][kk][1] = ex2_h2(s16[t][n0][1]);
                pa[t][kk][2] = ex2_h2(s16[t][n1][0]);
                pa[t][kk][3] = ex2_h2(s16[t][n1][1]);
            }

        #pragma unroll
        for (int kk = 0; kk < 4; ++kk) {
            #pragma unroll
            for (int g = 0; g < 4; ++g) {
                uint32_t vb[4];
                ldsm_x4t(vb, sV + v_lane + (uint32_t)(kk * 16 * KS_H * 2) + g * 32);
                #pragma unroll
                for (int t = 0; t < 2; ++t) {
                    mma_f16(o[t][2 * g],     pa[t][kk], vb[0], vb[1]);
                    mma_f16(o[t][2 * g + 1], pa[t][kk], vb[2], vb[3]);
                }
            }
            #pragma unroll
            for (int t = 0; t < 2; ++t)
                mma_f16(lacc[t], pa[t][kk], ONES_H2, ONES_H2);
        }

        if (++stg == N_STG) stg = 0;
    }

    #pragma unroll
    for (int t = 0; t < 2; ++t) {
        float inv_lo = 1.0f / lacc[t][0];
        float inv_hi = 1.0f / lacc[t][2];
        int row = q0 + m0 + t * 16 + lr;
        #pragma unroll
        for (int n = 0; n < 8; ++n) {
            int col = h * HD + n * 8 + 2 * lc;
            *(__half2*)(outh + (size_t)row * EMB + col) =
                h2(o[t][n][0] * inv_lo, o[t][n][1] * inv_lo);
            *(__half2*)(outh + (size_t)(row + 8) * EMB + col) =
                h2(o[t][n][2] * inv_hi, o[t][n][3] * inv_hi);
        }
    }
}

// ---------------------------------------------------------------------------
extern "C" void kernel_launch(void* const* d_in, const int* in_sizes, int n_in,
                              void* d_out, int out_size)
{
    const float* x     = (const float*)d_in[0];
    const float* w_qkv = (const float*)d_in[1];
    const float* b_qkv = (const float*)d_in[2];
    const float* w_out = (const float*)d_in[3];
    const float* b_out = (const float*)d_in[4];
    float* out = (float*)d_out;

    __half *xh, *qkv_h, *attn_h, *wqkv_t, *wout_t;
    cudaGetSymbolAddress((void**)&xh,     g_x_h);
    cudaGetSymbolAddress((void**)&qkv_h,  g_qkv_h);
    cudaGetSymbolAddress((void**)&attn_h, g_attn_h);
    cudaGetSymbolAddress((void**)&wqkv_t, g_wqkv_t);
    cudaGetSymbolAddress((void**)&wout_t, g_wout_t);

    // 0) Conversions
    f32_to_h<<<(S_LEN * EMB) / (256 * 4), 256>>>(x, xh);
    transpose_to_half<<<dim3(QKV_N / 32, EMB / 32), dim3(32, 8)>>>(w_qkv, wqkv_t, EMB, QKV_N);
    transpose_to_half<<<dim3(EMB / 32,  EMB / 32), dim3(32, 8)>>>(w_out, wout_t, EMB, EMB);

    // 1) QKV projection (Q cols pre-scaled by QSCALE)
    {
        cudaFuncSetAttribute(gemm_f16<0>,
                             cudaFuncAttributeMaxDynamicSharedMemorySize, GEMM_SMEM);
        dim3 grid(QKV_N / 128, S_LEN / 128);
        gemm_f16<0><<<grid, 256, GEMM_SMEM>>>(xh, wqkv_t, b_qkv, qkv_h,
                                              S_LEN, QKV_N, EMB);
    }

    // 2) Flash attention (ring-3, 3 CTA/SM, single wave)
    {
        cudaFuncSetAttribute(attn_f16,
                             cudaFuncAttributeMaxDynamicSharedMemorySize, SM_ATT);
        dim3 grid(S_LEN / 128, NH);
        attn_f16<<<grid, 128, SM_ATT>>>(qkv_h, attn_h);
    }

    // 3) Output projection -> fp32
    {
        cudaFuncSetAttribute(gemm_f16<1>,
                             cudaFuncAttributeMaxDynamicSharedMemorySize, GEMM_SMEM);
        dim3 grid(EMB / 128, S_LEN / 128);
        gemm_f16<1><<<grid, 256, GEMM_SMEM>>>(attn_h, wout_t, b_out, out,
                                              S_LEN, EMB, EMB);
    }
}